// round 1
// baseline (speedup 1.0000x reference)
#include <cuda_runtime.h>
#include <cstdint>

#define TT 2048
#define UNR 8

__device__ __forceinline__ float tanh_ap(float x){ float r; asm("tanh.approx.f32 %0, %1;" : "=f"(r) : "f"(x)); return r; }
__device__ __forceinline__ float ex2_ap (float x){ float r; asm("ex2.approx.f32 %0, %1;"  : "=f"(r) : "f"(x)); return r; }
__device__ __forceinline__ float rcp_ap (float x){ float r; asm("rcp.approx.f32 %0, %1;"  : "=f"(r) : "f"(x)); return r; }
__device__ __forceinline__ float sqrt_ap(float x){ float r; asm("sqrt.approx.f32 %0, %1;" : "=f"(r) : "f"(x)); return r; }
__device__ __forceinline__ float clampf(float x, float lo, float hi){ return fminf(fmaxf(x, lo), hi); }

struct Consts {
  float insc, Cc, Sc, Sinv, kexp, sub, crak, rk, lg, kr, ls;
};

// Full pass-2 Q computation (used once per thread, for t==0 with rolled/final states)
__device__ __forceinline__ float q_final(float Prec, float PET, float RSmax, float Area,
                                         float SMS1r, float GW1r, float RSr, const Consts& c)
{
  float IMAX = fmaxf(fminf(c.insc, PET), 0.f);
  float INTC = fmaxf(fminf(IMAX, Prec), 0.f);
  float INR  = fmaxf(Prec - INTC, 0.f);
  float SMS1c = fmaxf(fminf(SMS1r, c.Sc), 0.f);
  float infil = c.Cc * ex2_ap(c.kexp * SMS1c);
  float t1 = tanh_ap(1e7f * (infil - INR));
  float h1 = fmaf(t1, 0.5f, 0.5f), h1n = fmaf(t1, -0.5f, 0.5f);
  float RMO = fmaxf(h1 * INR + h1n * infil, 0.f);
  float IRUN = fmaxf(INR - RMO, 0.f);
  float ratio = SMS1c * c.Sinv;
  float SRUN = fmaxf(c.sub * ratio * RMO, 0.f);
  float t4 = tanh_ap(1e7f * GW1r);
  float h4 = fmaf(t4, 0.5f, 0.5f);
  float BAS = fmaxf(h4 * (c.rk * GW1r), 0.f);
  float inflow = (IRUN + SRUN + BAS) * Area;
  float x5 = RSr + inflow - RSmax;
  float t5 = tanh_ap(1e7f * x5);
  float h5 = fmaf(t5, 0.5f, 0.5f), h5n = fmaf(t5, -0.5f, 0.5f);
  float Qor = fmaxf(h5 * x5, 0.f);
  float r = RSr * rcp_ap(RSmax);
  float pw = r * sqrt_ap(r);
  float Qir = fmaxf(h5 * (c.kr * RSmax) + h5n * (c.kr * RSr) * pw, 0.f);
  float drarg = (SRUN + IRUN) * (1.f - Area) + Qir + Qor - c.ls;
  float t7 = tanh_ap(1e7f * drarg);
  float h7 = fmaf(t7, 0.5f, 0.5f);
  float DR = fmaxf(h7 * drarg, 0.f);
  float GD = BAS * (1.f - Area);
  return fmaxf(DR + GD, 0.f);
}

__global__ void __launch_bounds__(32, 1)
hirnn_kernel(const float4* __restrict__ xin_all,
             const float* __restrict__ pINSC, const float* __restrict__ pCOEFF,
             const float* __restrict__ pSQ,   const float* __restrict__ pSMSC,
             const float* __restrict__ pSUB,  const float* __restrict__ pCRAK,
             const float* __restrict__ pRecK, const float* __restrict__ pKr,
             const float* __restrict__ pLG,   const float* __restrict__ pLS,
             float* __restrict__ out, int B)
{
  int b = blockIdx.x * 32 + threadIdx.x;
  if (b >= B) return;

  Consts c;
  c.insc = clampf(pINSC[0] * 5.f, 0.5f, 5.f);
  c.Cc   = clampf(pCOEFF[0] * 400.f, 50.f, 400.f);
  float qv = clampf(pSQ[0] * 6.f, 0.f, 6.f);
  c.Sc   = clampf(pSMSC[0] * 500.f, 50.f, 500.f);
  c.Sinv = 1.f / c.Sc;
  c.kexp = -qv * c.Sinv * 1.4426950408889634f;   // exp(-q*s/S) == exp2(kexp*s)
  c.sub  = clampf(pSUB[0], 0.f, 1.f);
  c.crak = clampf(pCRAK[0], 0.f, 1.f);
  c.rk   = clampf(pRecK[0] * 0.3f, 0.003f, 0.3f);
  c.lg   = clampf(pLG[0] * 0.1f, 0.001f, 0.1f);
  c.kr   = clampf(pKr[0] * 0.1f, 0.01f, 0.1f);
  c.ls   = clampf(pLS[0] * 10.f, 0.01f, 10.f);

  const float4* __restrict__ xin = xin_all + (size_t)b * TT;
  float* __restrict__ op = out + (size_t)b * TT;

  float SMS = 0.f, GW = 0.f, RS = 0.f;
  float rs0 = 0.f;
  float4 x0 = xin[0];

  float4 buf[UNR], nbuf[UNR];
#pragma unroll
  for (int i = 0; i < UNR; i++) buf[i] = xin[i];

  float qb0 = 0.f, qb1 = 0.f, qb2 = 0.f, qb3 = 0.f;

  for (int g = 0; g < TT; g += UNR) {
    // prefetch next group (hides DRAM latency behind ~1000 cycles of compute)
    if (g + UNR < TT) {
#pragma unroll
      for (int i = 0; i < UNR; i++) nbuf[i] = xin[g + UNR + i];
    }
#pragma unroll
    for (int i = 0; i < UNR; i++) {
      float Prec = buf[i].x, PET = buf[i].y, RSmax = buf[i].z, Area = buf[i].w;

      // interception
      float IMAX = fmaxf(fminf(c.insc, PET), 0.f);
      float INTC = fmaxf(fminf(IMAX, Prec), 0.f);
      float INR  = fmaxf(Prec - INTC, 0.f);
      // sms store (clamp incoming state)
      float SMS1c = fmaxf(fminf(SMS, c.Sc), 0.f);
      // soil fluxes
      float infil = c.Cc * ex2_ap(c.kexp * SMS1c);
      float t1 = tanh_ap(1e7f * (infil - INR));
      float h1 = fmaf(t1, 0.5f, 0.5f), h1n = fmaf(t1, -0.5f, 0.5f);
      float RMO = fmaxf(h1 * INR + h1n * infil, 0.f);
      float IRUN = fmaxf(INR - RMO, 0.f);
      float ratio = SMS1c * c.Sinv;
      float SRUN = fmaxf(c.sub * ratio * RMO, 0.f);
      float RmS = RMO - SRUN;
      float REC = fmaxf(c.crak * ratio * RmS, 0.f);
      float SMF = fmaxf(RmS - REC, 0.f);
      float POT = fmaxf(PET - INTC, 0.f);
      float cap = 10.f * ratio;
      float t2 = tanh_ap(1e7f * (cap - POT));
      float h2 = fmaf(t2, 0.5f, 0.5f), h2n = fmaf(t2, -0.5f, 0.5f);
      float ETS = fmaxf(h2 * POT + h2n * cap, 0.f);
      // next SMS
      float SMSn = SMS1c + clampf(SMF - ETS, -100000.f, 100000.f);
      // recharge
      float xr = SMS1c + SMF - ETS - c.Sc;
      float t3 = tanh_ap(1e7f * xr);
      float h3 = fmaf(t3, 0.5f, 0.5f), h3n = fmaf(t3, -0.5f, 0.5f);
      float RECn = fmaxf(h3 * (REC + xr) + h3n * REC, 0.f);
      // gw store
      float t4g = tanh_ap(1e7f * GW);
      float h4 = fmaf(t4g, 0.5f, 0.5f);
      float BAS = fmaxf(h4 * (c.rk * GW), 0.f);
      float GWn = (GW - c.lg) + clampf(RECn - BAS, -100000.f, 100000.f);
      // release (with incoming RS)
      float inflow = (IRUN + SRUN + BAS) * Area;
      float x5 = RS + inflow - RSmax;
      float t5 = tanh_ap(1e7f * x5);
      float h5 = fmaf(t5, 0.5f, 0.5f), h5n = fmaf(t5, -0.5f, 0.5f);
      float Qor = fmaxf(h5 * x5, 0.f);
      float rcpR = rcp_ap(RSmax);
      float r5 = RS * rcpR;
      float p5 = r5 * sqrt_ap(r5);
      float Qir = fmaxf(h5 * (c.kr * RSmax) + h5n * (c.kr * RS) * p5, 0.f);
      float Qri = fmaxf(inflow, 0.f);
      float RSn = RS + clampf(Qri - Qor - Qir, -100000.f, 100000.f);

      // ---- pass-2 output Q for this t (valid for t>=1; t==0 patched later).
      // Reuses INR/IRUN/SRUN/BAS/inflow (identical operands as reference pass-2),
      // re-derives release with the POST-step RS (outs[:,t,2]).
      float x6 = RSn + inflow - RSmax;
      float t6 = tanh_ap(1e7f * x6);
      float h6 = fmaf(t6, 0.5f, 0.5f), h6n = fmaf(t6, -0.5f, 0.5f);
      float Qor2 = fmaxf(h6 * x6, 0.f);
      float r6 = RSn * rcpR;
      float p6 = r6 * sqrt_ap(r6);
      float Qir2 = fmaxf(h6 * (c.kr * RSmax) + h6n * (c.kr * RSn) * p6, 0.f);
      float drarg = (SRUN + IRUN) * (1.f - Area) + Qir2 + Qor2 - c.ls;
      float t7 = tanh_ap(1e7f * drarg);
      float h7 = fmaf(t7, 0.5f, 0.5f);
      float DR = fmaxf(h7 * drarg, 0.f);
      float GD = BAS * (1.f - Area);
      float Q = fmaxf(DR + GD, 0.f);

      SMS = SMSn; GW = GWn; RS = RSn;
      if (g + i == 0) rs0 = RSn;

      if      ((i & 3) == 0) qb0 = Q;
      else if ((i & 3) == 1) qb1 = Q;
      else if ((i & 3) == 2) qb2 = Q;
      else {
        qb3 = Q;
        *reinterpret_cast<float4*>(op + g + (i - 3)) = make_float4(qb0, qb1, qb2, qb3);
      }
    }
#pragma unroll
    for (int i = 0; i < UNR; i++) buf[i] = nbuf[i];
  }

  // Q[b,0]: jnp.roll wraps -> SMS1/GW1 are the FINAL states; RS is outs[b,0,2]
  op[0] = q_final(x0.x, x0.y, x0.z, x0.w, SMS, GW, rs0, c);
}

extern "C" void kernel_launch(void* const* d_in, const int* in_sizes, int n_in,
                              void* d_out, int out_size) {
  const float4* xin = (const float4*)d_in[0];
  int B = out_size / TT;
  int grid = (B + 31) / 32;
  hirnn_kernel<<<grid, 32>>>(xin,
      (const float*)d_in[1], (const float*)d_in[2], (const float*)d_in[3],
      (const float*)d_in[4], (const float*)d_in[5], (const float*)d_in[6],
      (const float*)d_in[7], (const float*)d_in[8], (const float*)d_in[9],
      (const float*)d_in[10],
      (float*)d_out, B);
}

// round 2
// speedup vs baseline: 1.3841x; 1.3841x over previous
#include <cuda_runtime.h>
#include <cstdint>

#define TT 2048
#define UNR 8

__device__ __forceinline__ float ex2_ap (float x){ float r; asm("ex2.approx.f32 %0, %1;"  : "=f"(r) : "f"(x)); return r; }
__device__ __forceinline__ float rcp_ap (float x){ float r; asm("rcp.approx.f32 %0, %1;"  : "=f"(r) : "f"(x)); return r; }
__device__ __forceinline__ float sqrt_ap(float x){ float r; asm("sqrt.approx.f32 %0, %1;" : "=f"(r) : "f"(x)); return r; }
__device__ __forceinline__ float clampf(float x, float lo, float hi){ return fminf(fmaxf(x, lo), hi); }
__device__ __forceinline__ float relu(float x){ return fmaxf(x, 0.f); }

struct Consts {
  float insc, Cc, Sc, Sinv, kexp, sub, crak, rk, lg, kr, ls;
};

// Full pass-2 Q (used once per thread for t==0: rolled SMS/GW = FINAL states, RS = outs[b,0,2])
__device__ __forceinline__ float q_final(float Prec, float PET, float RSmax, float Area,
                                         float SMS1r, float GW1r, float RSr, const Consts& c)
{
  float IMAX = fmaxf(fminf(c.insc, PET), 0.f);
  float INTC = fmaxf(fminf(IMAX, Prec), 0.f);
  float INR  = relu(Prec - INTC);
  float SMS1c = fmaxf(fminf(SMS1r, c.Sc), 0.f);
  float infil = c.Cc * ex2_ap(c.kexp * SMS1c);
  float RMO = fminf(INR, infil);
  float IRUN = INR - RMO;
  float ratio = SMS1c * c.Sinv;
  float SRUN = c.sub * ratio * RMO;
  float BAS = c.rk * relu(GW1r);
  float inflow = (IRUN + SRUN + BAS) * Area;
  float x5 = RSr + inflow - RSmax;
  float Qor = relu(x5);
  float r = relu(RSr) * rcp_ap(RSmax);
  float pw = r * sqrt_ap(r);
  float Qir = (x5 > 0.f) ? (c.kr * RSmax) : (c.kr * RSr * pw);
  float drarg = (SRUN + IRUN) * (1.f - Area) + Qir + Qor - c.ls;
  float DR = relu(drarg);
  float GD = BAS * (1.f - Area);
  return relu(DR + GD);
}

__global__ void __launch_bounds__(32, 1)
hirnn_kernel(const float4* __restrict__ xin_all,
             const float* __restrict__ pINSC, const float* __restrict__ pCOEFF,
             const float* __restrict__ pSQ,   const float* __restrict__ pSMSC,
             const float* __restrict__ pSUB,  const float* __restrict__ pCRAK,
             const float* __restrict__ pRecK, const float* __restrict__ pKr,
             const float* __restrict__ pLG,   const float* __restrict__ pLS,
             float* __restrict__ out, int B)
{
  int b = blockIdx.x * 32 + threadIdx.x;
  if (b >= B) return;

  Consts c;
  c.insc = clampf(pINSC[0] * 5.f, 0.5f, 5.f);
  c.Cc   = clampf(pCOEFF[0] * 400.f, 50.f, 400.f);
  float qv = clampf(pSQ[0] * 6.f, 0.f, 6.f);
  c.Sc   = clampf(pSMSC[0] * 500.f, 50.f, 500.f);
  c.Sinv = 1.f / c.Sc;
  c.kexp = -qv * c.Sinv * 1.4426950408889634f;   // exp(-q*s/S) == exp2(kexp*s)
  c.sub  = clampf(pSUB[0], 0.f, 1.f);
  c.crak = clampf(pCRAK[0], 0.f, 1.f);
  c.rk   = clampf(pRecK[0] * 0.3f, 0.003f, 0.3f);
  c.lg   = clampf(pLG[0] * 0.1f, 0.001f, 0.1f);
  c.kr   = clampf(pKr[0] * 0.1f, 0.01f, 0.1f);
  c.ls   = clampf(pLS[0] * 10.f, 0.01f, 10.f);

  const float4* __restrict__ xin = xin_all + (size_t)b * TT;
  float* __restrict__ op = out + (size_t)b * TT;

  float SMS = 0.f, GW = 0.f, RS = 0.f;
  float rs0 = 0.f;
  float4 x0 = xin[0];

  float4 buf[UNR], nbuf[UNR];
#pragma unroll
  for (int i = 0; i < UNR; i++) buf[i] = xin[i];

  float qb0 = 0.f, qb1 = 0.f, qb2 = 0.f, qb3 = 0.f;

  for (int g = 0; g < TT; g += UNR) {
    if (g + UNR < TT) {
#pragma unroll
      for (int i = 0; i < UNR; i++) nbuf[i] = xin[g + UNR + i];
    }
#pragma unroll
    for (int i = 0; i < UNR; i++) {
      float Prec = buf[i].x, PET = buf[i].y, RSmax = buf[i].z, Area = buf[i].w;

      // interception (input-only, off-chain)
      float IMAX = fmaxf(fminf(c.insc, PET), 0.f);
      float INTC = fmaxf(fminf(IMAX, Prec), 0.f);
      float INR  = relu(Prec - INTC);
      float POT  = relu(PET - INTC);

      // SMS recurrence chain
      float SMS1c = fmaxf(fminf(SMS, c.Sc), 0.f);
      float ratio = SMS1c * c.Sinv;
      float infil = c.Cc * ex2_ap(c.kexp * SMS1c);       // MUFU on chain
      float sr      = c.sub  * ratio;                     // parallel with ex2
      float one_msr = 1.f - sr;
      float cr      = c.crak * ratio;
      float one_mcr = 1.f - cr;
      float cap = 10.f * ratio;
      float ETS = fminf(POT, cap);                        // ready early
      float base = SMS1c - ETS;                           // ready early
      float baseS = base - c.Sc;                          // for recharge

      float RMO  = fminf(INR, infil);
      float IRUN = INR - RMO;
      float SRUN = sr * RMO;
      float RmS  = one_msr * RMO;          // RMO - SRUN (>=0)
      float REC  = cr * RmS;               // >= 0
      float SMF  = one_mcr * RmS;          // RmS - REC (>=0)
      float SMSn = base + SMF;             // clip(+-1e5) never binds

      // recharge + gw
      float xr   = baseS + SMF;            // SMSn - Sc
      float RECn = REC + relu(xr);
      float BAS  = c.rk * relu(GW);
      float GWn  = (GW - c.lg - BAS) + RECn;

      // release with incoming RS
      float inflow = (IRUN + SRUN + BAS) * Area;
      float x5  = RS + inflow - RSmax;
      float Qor = relu(x5);
      float rcpR = rcp_ap(RSmax);
      float krRSmax = c.kr * RSmax;
      float r5 = relu(RS) * rcpR;
      float p5 = r5 * sqrt_ap(r5);
      float Qir = (x5 > 0.f) ? krRSmax : (c.kr * RS * p5);
      float RSn = RS + (inflow - Qor - Qir);   // Qri = relu(inflow) = inflow (>=0)

      // pass-2 output Q (t>=1 semantics; t==0 patched after loop)
      float x6  = RSn + inflow - RSmax;
      float Qor2 = relu(x6);
      float r6 = relu(RSn) * rcpR;
      float p6 = r6 * sqrt_ap(r6);
      float Qir2 = (x6 > 0.f) ? krRSmax : (c.kr * RSn * p6);
      float onemA = 1.f - Area;
      float drarg = (SRUN + IRUN) * onemA + Qir2 + Qor2 - c.ls;
      float DR = relu(drarg);
      float Q = relu(DR + BAS * onemA);

      SMS = SMSn; GW = GWn; RS = RSn;
      if (g + i == 0) rs0 = RSn;

      if      ((i & 3) == 0) qb0 = Q;
      else if ((i & 3) == 1) qb1 = Q;
      else if ((i & 3) == 2) qb2 = Q;
      else {
        qb3 = Q;
        *reinterpret_cast<float4*>(op + g + (i - 3)) = make_float4(qb0, qb1, qb2, qb3);
      }
    }
#pragma unroll
    for (int i = 0; i < UNR; i++) buf[i] = nbuf[i];
  }

  // Q[b,0]: jnp.roll wrap -> SMS1/GW1 = FINAL states; RS = outs[b,0,2]
  op[0] = q_final(x0.x, x0.y, x0.z, x0.w, SMS, GW, rs0, c);
}

extern "C" void kernel_launch(void* const* d_in, const int* in_sizes, int n_in,
                              void* d_out, int out_size) {
  const float4* xin = (const float4*)d_in[0];
  int B = out_size / TT;
  int grid = (B + 31) / 32;
  hirnn_kernel<<<grid, 32>>>(xin,
      (const float*)d_in[1], (const float*)d_in[2], (const float*)d_in[3],
      (const float*)d_in[4], (const float*)d_in[5], (const float*)d_in[6],
      (const float*)d_in[7], (const float*)d_in[8], (const float*)d_in[9],
      (const float*)d_in[10],
      (float*)d_out, B);
}

// round 3
// speedup vs baseline: 1.3847x; 1.0005x over previous
#include <cuda_runtime.h>
#include <cstdint>

#define TT 2048
#define UNR 8

__device__ __forceinline__ float ex2_ap (float x){ float r; asm("ex2.approx.f32 %0, %1;"  : "=f"(r) : "f"(x)); return r; }
__device__ __forceinline__ float rcp_ap (float x){ float r; asm("rcp.approx.f32 %0, %1;"  : "=f"(r) : "f"(x)); return r; }
__device__ __forceinline__ float sqrt_ap(float x){ float r; asm("sqrt.approx.f32 %0, %1;" : "=f"(r) : "f"(x)); return r; }
__device__ __forceinline__ float clampf(float x, float lo, float hi){ return fminf(fmaxf(x, lo), hi); }
__device__ __forceinline__ float relu(float x){ return fmaxf(x, 0.f); }

struct Consts {
  float insc, Cc, Sc, Sinv, kexp, sub, crak, rk, lg, kr, ls;
};

// Full pass-2 Q (used once per thread for t==0: rolled SMS/GW = FINAL states, RS = outs[b,0,2])
__device__ __forceinline__ float q_final(float Prec, float PET, float RSmax, float Area,
                                         float SMS1r, float GW1r, float RSr, const Consts& c)
{
  float IMAX = fmaxf(fminf(c.insc, PET), 0.f);
  float INTC = fmaxf(fminf(IMAX, Prec), 0.f);
  float INR  = relu(Prec - INTC);
  float SMS1c = fmaxf(fminf(SMS1r, c.Sc), 0.f);
  float infil = c.Cc * ex2_ap(c.kexp * SMS1c);
  float RMO = fminf(INR, infil);
  float IRUN = INR - RMO;
  float ratio = SMS1c * c.Sinv;
  float SRUN = c.sub * ratio * RMO;
  float BAS = c.rk * relu(GW1r);
  float inflow = (IRUN + SRUN + BAS) * Area;
  float x5 = RSr + inflow - RSmax;
  float Qor = relu(x5);
  float r = relu(RSr) * rcp_ap(RSmax);
  float pw = r * sqrt_ap(r);
  float Qir = (x5 > 0.f) ? (c.kr * RSmax) : (c.kr * RSr * pw);
  float drarg = (SRUN + IRUN) * (1.f - Area) + Qir + Qor - c.ls;
  float DR = relu(drarg);
  float GD = BAS * (1.f - Area);
  return relu(DR + GD);
}

__global__ void __launch_bounds__(32, 1)
hirnn_kernel(const float4* __restrict__ xin_all,
             const float* __restrict__ pINSC, const float* __restrict__ pCOEFF,
             const float* __restrict__ pSQ,   const float* __restrict__ pSMSC,
             const float* __restrict__ pSUB,  const float* __restrict__ pCRAK,
             const float* __restrict__ pRecK, const float* __restrict__ pKr,
             const float* __restrict__ pLG,   const float* __restrict__ pLS,
             float* __restrict__ out, int B)
{
  int b = blockIdx.x * 32 + threadIdx.x;
  if (b >= B) return;

  Consts c;
  c.insc = clampf(pINSC[0] * 5.f, 0.5f, 5.f);
  c.Cc   = clampf(pCOEFF[0] * 400.f, 50.f, 400.f);
  float qv = clampf(pSQ[0] * 6.f, 0.f, 6.f);
  c.Sc   = clampf(pSMSC[0] * 500.f, 50.f, 500.f);
  c.Sinv = 1.f / c.Sc;
  c.kexp = -qv * c.Sinv * 1.4426950408889634f;   // exp(-q*s/S) == exp2(kexp*s)
  c.sub  = clampf(pSUB[0], 0.f, 1.f);
  c.crak = clampf(pCRAK[0], 0.f, 1.f);
  c.rk   = clampf(pRecK[0] * 0.3f, 0.003f, 0.3f);
  c.lg   = clampf(pLG[0] * 0.1f, 0.001f, 0.1f);
  c.kr   = clampf(pKr[0] * 0.1f, 0.01f, 0.1f);
  c.ls   = clampf(pLS[0] * 10.f, 0.01f, 10.f);

  const float4* __restrict__ xin = xin_all + (size_t)b * TT;
  float* __restrict__ op = out + (size_t)b * TT;

  float SMS = 0.f, GW = 0.f, RS = 0.f;
  float rs0 = 0.f;
  float4 x0 = xin[0];

  float4 buf[UNR], nbuf[UNR];
#pragma unroll
  for (int i = 0; i < UNR; i++) buf[i] = xin[i];

  float qb0 = 0.f, qb1 = 0.f, qb2 = 0.f, qb3 = 0.f;

  for (int g = 0; g < TT; g += UNR) {
    if (g + UNR < TT) {
#pragma unroll
      for (int i = 0; i < UNR; i++) nbuf[i] = xin[g + UNR + i];
    }
#pragma unroll
    for (int i = 0; i < UNR; i++) {
      float Prec = buf[i].x, PET = buf[i].y, RSmax = buf[i].z, Area = buf[i].w;

      // interception (input-only, off-chain)
      float IMAX = fmaxf(fminf(c.insc, PET), 0.f);
      float INTC = fmaxf(fminf(IMAX, Prec), 0.f);
      float INR  = relu(Prec - INTC);
      float POT  = relu(PET - INTC);

      // SMS recurrence chain
      float SMS1c = fmaxf(fminf(SMS, c.Sc), 0.f);
      float ratio = SMS1c * c.Sinv;
      float infil = c.Cc * ex2_ap(c.kexp * SMS1c);       // MUFU on chain
      float sr      = c.sub  * ratio;                     // parallel with ex2
      float one_msr = 1.f - sr;
      float cr      = c.crak * ratio;
      float one_mcr = 1.f - cr;
      float cap = 10.f * ratio;
      float ETS = fminf(POT, cap);                        // ready early
      float base = SMS1c - ETS;                           // ready early
      float baseS = base - c.Sc;                          // for recharge

      float RMO  = fminf(INR, infil);
      float IRUN = INR - RMO;
      float SRUN = sr * RMO;
      float RmS  = one_msr * RMO;          // RMO - SRUN (>=0)
      float REC  = cr * RmS;               // >= 0
      float SMF  = one_mcr * RmS;          // RmS - REC (>=0)
      float SMSn = base + SMF;             // clip(+-1e5) never binds

      // recharge + gw
      float xr   = baseS + SMF;            // SMSn - Sc
      float RECn = REC + relu(xr);
      float BAS  = c.rk * relu(GW);
      float GWn  = (GW - c.lg - BAS) + RECn;

      // release with incoming RS
      float inflow = (IRUN + SRUN + BAS) * Area;
      float x5  = RS + inflow - RSmax;
      float Qor = relu(x5);
      float rcpR = rcp_ap(RSmax);
      float krRSmax = c.kr * RSmax;
      float r5 = relu(RS) * rcpR;
      float p5 = r5 * sqrt_ap(r5);
      float Qir = (x5 > 0.f) ? krRSmax : (c.kr * RS * p5);
      float RSn = RS + (inflow - Qor - Qir);   // Qri = relu(inflow) = inflow (>=0)

      // pass-2 output Q (t>=1 semantics; t==0 patched after loop)
      float x6  = RSn + inflow - RSmax;
      float Qor2 = relu(x6);
      float r6 = relu(RSn) * rcpR;
      float p6 = r6 * sqrt_ap(r6);
      float Qir2 = (x6 > 0.f) ? krRSmax : (c.kr * RSn * p6);
      float onemA = 1.f - Area;
      float drarg = (SRUN + IRUN) * onemA + Qir2 + Qor2 - c.ls;
      float DR = relu(drarg);
      float Q = relu(DR + BAS * onemA);

      SMS = SMSn; GW = GWn; RS = RSn;
      if (g + i == 0) rs0 = RSn;

      if      ((i & 3) == 0) qb0 = Q;
      else if ((i & 3) == 1) qb1 = Q;
      else if ((i & 3) == 2) qb2 = Q;
      else {
        qb3 = Q;
        *reinterpret_cast<float4*>(op + g + (i - 3)) = make_float4(qb0, qb1, qb2, qb3);
      }
    }
#pragma unroll
    for (int i = 0; i < UNR; i++) buf[i] = nbuf[i];
  }

  // Q[b,0]: jnp.roll wrap -> SMS1/GW1 = FINAL states; RS = outs[b,0,2]
  op[0] = q_final(x0.x, x0.y, x0.z, x0.w, SMS, GW, rs0, c);
}

extern "C" void kernel_launch(void* const* d_in, const int* in_sizes, int n_in,
                              void* d_out, int out_size) {
  const float4* xin = (const float4*)d_in[0];
  int B = out_size / TT;
  int grid = (B + 31) / 32;
  hirnn_kernel<<<grid, 32>>>(xin,
      (const float*)d_in[1], (const float*)d_in[2], (const float*)d_in[3],
      (const float*)d_in[4], (const float*)d_in[5], (const float*)d_in[6],
      (const float*)d_in[7], (const float*)d_in[8], (const float*)d_in[9],
      (const float*)d_in[10],
      (float*)d_out, B);
}